// round 17
// baseline (speedup 1.0000x reference)
#include <cuda_runtime.h>
#include <cuda_fp16.h>
#include <cstdint>

// Problem dims
#define NROWS 16384
#define UDIM  4096
#define KDIM  1024

// GEMM tiling (fp16: 64 elements per 128-byte k-tile row)
#define BM 128
#define BN 128
#define K_TILES 16                // 1024 / 64
#define STAGES 2
#define TOTAL_TILES ((NROWS / BM) * (UDIM / BN))   // 4096

#define TILE_BYTES 16384                       // one 128-row x 128B tile
#define STAGE_BYTES (2 * TILE_BYTES)           // A + B = 32 KB
#define SMEM_DATA 1024
#define SMEM_TOTAL (SMEM_DATA + STAGES * STAGE_BYTES)   // 66560 -> 3 CTAs/SM

// ------------------- scratch (pre-swizzled, tiled fp16 operands + norms) -------------------
__device__ __align__(256) __half g_A[(size_t)NROWS * KDIM];  // 32 MB
__device__ __align__(256) __half g_B[(size_t)UDIM  * KDIM];  // 8 MB
__device__ float g_xsq[NROWS];
__device__ float g_wsq[UDIM];

// ------------------- PTX helpers -------------------
#define MBAR_INIT(addr, cnt) \
    asm volatile("mbarrier.init.shared.b64 [%0], %1;" :: "r"(addr), "r"((uint32_t)(cnt)) : "memory")

#define MBAR_EXPECT_TX(addr, bytes) \
    asm volatile("mbarrier.arrive.expect_tx.shared.b64 _, [%0], %1;" \
                 :: "r"(addr), "r"((uint32_t)(bytes)) : "memory")

#define MBAR_ARRIVE(addr) \
    asm volatile("mbarrier.arrive.shared.b64 _, [%0];" :: "r"(addr) : "memory")

#define MBAR_WAIT(addr, parity) do {                                                   \
    uint32_t _mb = (addr); uint32_t _ph = (parity); uint32_t _done;                    \
    asm volatile("{\n\t.reg .pred p;\n\t"                                              \
        "mbarrier.try_wait.parity.acquire.cta.shared::cta.b64 p, [%1], %2;\n\t"        \
        "selp.b32 %0, 1, 0, p;\n\t}"                                                   \
        : "=r"(_done) : "r"(_mb), "r"(_ph) : "memory");                                \
    if (!_done) {                                                                      \
        asm volatile("{\n\t.reg .pred P1;\n\t"                                         \
            "WL%=:\n\t"                                                                \
            "mbarrier.try_wait.parity.acquire.cta.shared::cta.b64 P1, [%0], %1, 0x989680;\n\t" \
            "@P1 bra.uni WD%=;\n\t"                                                    \
            "bra.uni WL%=;\n\t"                                                        \
            "WD%=:\n\t}"                                                               \
            :: "r"(_mb), "r"(_ph) : "memory");                                         \
    }                                                                                  \
} while (0)

__device__ __forceinline__ void bulk_g2s(uint32_t dst, const void* src, uint32_t bytes, uint32_t mbar) {
    asm volatile("cp.async.bulk.shared::cta.global.mbarrier::complete_tx::bytes [%0], [%1], %2, [%3];"
                 :: "r"(dst), "l"(src), "r"(bytes), "r"(mbar) : "memory");
}

__device__ __forceinline__ void ldsm4(uint32_t& r0, uint32_t& r1, uint32_t& r2, uint32_t& r3,
                                      uint32_t addr) {
    asm volatile("ldmatrix.sync.aligned.m8n8.x4.shared.b16 {%0,%1,%2,%3}, [%4];"
                 : "=r"(r0), "=r"(r1), "=r"(r2), "=r"(r3) : "r"(addr));
}

// fp16 MMA with fp16 accumulation: 2 acc regs (4 halves)
__device__ __forceinline__ void mma_f16acc(uint32_t* c, const uint32_t* a, const uint32_t* b) {
    asm volatile(
        "mma.sync.aligned.m16n8k16.row.col.f16.f16.f16.f16 "
        "{%0,%1}, {%2,%3,%4,%5}, {%6,%7}, {%0,%1};"
        : "+r"(c[0]), "+r"(c[1])
        : "r"(a[0]), "r"(a[1]), "r"(a[2]), "r"(a[3]), "r"(b[0]), "r"(b[1]));
}

// ------------------- prepass: fp32 -> fp16, pre-tiled + SW128-swizzled, fused row norms -------------------
// Warp-per-row: 8 warps/block, 8 float4 loads/lane, warp-shuffle reduce only.
__global__ void __launch_bounds__(256) convert_kernel(const float* __restrict__ x,
                                                      const float* __restrict__ w) {
    int wid = threadIdx.x >> 5, lane = threadIdx.x & 31;
    int row = blockIdx.x * 8 + wid;
    const float* src;
    __half* dst;
    float* sq;
    if (row < NROWS) { src = x; dst = g_A; sq = g_xsq; }
    else { row -= NROWS; src = w; dst = g_B; sq = g_wsq; }

    int rt = row >> 7, r = row & 127;
    const float4* srow = reinterpret_cast<const float4*>(src + (size_t)row * KDIM);
    char* tbase0 = reinterpret_cast<char*>(dst) + (size_t)(rt * K_TILES) * TILE_BYTES;

    float s = 0.f;
    #pragma unroll
    for (int it = 0; it < 8; it++) {
        int idx = it * 128 + lane * 4;           // element index within the row
        float4 v = srow[it * 32 + lane];
        s += v.x * v.x + v.y * v.y + v.z * v.z + v.w * v.w;

        int kt = idx >> 6;
        int c  = idx & 63;
        uint32_t off = (uint32_t)(r * 128 + c * 2);
        uint32_t swz = off ^ ((off >> 3) & 0x70);

        __half2 lo = __floats2half2_rn(v.x, v.y);
        __half2 hi = __floats2half2_rn(v.z, v.w);
        uint2 packed;
        packed.x = *reinterpret_cast<uint32_t*>(&lo);
        packed.y = *reinterpret_cast<uint32_t*>(&hi);
        *reinterpret_cast<uint2*>(tbase0 + (size_t)kt * TILE_BYTES + swz) = packed;
    }

    #pragma unroll
    for (int o = 16; o > 0; o >>= 1) s += __shfl_xor_sync(0xffffffffu, s, o);
    if (lane == 0) sq[row] = s;
}

// ------------------- persistent GEMM: out[m,u] = xsq[m] + wsq[u] - 2 * sum_k A B -------------------
// 128 threads, 3 CTAs/SM, persistent; the 2-stage pipeline flows continuously across
// tiles (global step g). Cross-tile prime at ks=3 works unchanged because fragment
// offsets are stage-relative. Producer rotates across warps by g.
__global__ void __launch_bounds__(128, 3) gemm_kernel(float* __restrict__ out) {
    extern __shared__ __align__(1024) char smem[];
    uint32_t sb = (uint32_t)__cvta_generic_to_shared(smem);
    uint32_t sdata = sb + SMEM_DATA;

    int tid = threadIdx.x;
    int wid = tid >> 5, lane = tid & 31;
    int wm = wid & 1;        // 0..1 -> M offset wm*64
    int wn = wid >> 1;       // 0..1 -> N offset wn*64
    int bid = blockIdx.x;
    int grid = gridDim.x;

    int ntiles = (TOTAL_TILES - bid + grid - 1) / grid;
    int total_steps = ntiles * K_TILES;

    uint32_t full0  = sb;                 // STAGES barriers, 8B each
    uint32_t empty0 = sb + STAGES * 8;

    if (tid == 0) {
        #pragma unroll
        for (int s = 0; s < STAGES; s++) {
            MBAR_INIT(full0  + s * 8, 1);
            MBAR_INIT(empty0 + s * 8, 4);   // one arrive per warp
        }
    }
    __syncthreads();

    // prologue: issue step 0 (tile bid, kt 0)
    if (tid == 0) {
        const char* pA = (const char*)g_A + (size_t)((bid & 127) * K_TILES) * TILE_BYTES;
        const char* pB = (const char*)g_B + (size_t)((bid >> 7) * K_TILES) * TILE_BYTES;
        MBAR_EXPECT_TX(full0, STAGE_BYTES);
        bulk_g2s(sdata,              pA, TILE_BYTES, full0);
        bulk_g2s(sdata + TILE_BYTES, pB, TILE_BYTES, full0);
    }

    // per-lane ldmatrix addressing
    int lr = lane & 15;                          // row within 16-row fragment
    uint32_t lh = (uint32_t)((lane >> 4) << 4);  // 0 or 16 (k-half bytes)
    uint32_t rxor = (uint32_t)((lr & 7) << 4);   // SW128 xor (frag bases are mult of 8 rows)
    uint32_t arow0 = (uint32_t)((wm * 64 + lr) * 128);
    uint32_t brow0 = (uint32_t)((wn * 64 + lr) * 128);

    uint32_t a[2][4][4];          // [buf][frag i][reg]
    uint32_t b[2][8][2];          // [buf][frag j][reg]

    // prologue: wait step 0, prime buffer 0
    MBAR_WAIT(full0, 0);
    {
        uint32_t abase = sdata + arow0;
        uint32_t bbase = sdata + TILE_BYTES + brow0;
        uint32_t col = lh ^ rxor;
        #pragma unroll
        for (int i = 0; i < 4; i++)
            ldsm4(a[0][i][0], a[0][i][1], a[0][i][2], a[0][i][3],
                  abase + (uint32_t)(i * 16 * 128) + col);
        #pragma unroll
        for (int q = 0; q < 4; q++) {
            uint32_t r0, r1, r2, r3;
            ldsm4(r0, r1, r2, r3, bbase + (uint32_t)(q * 16 * 128) + col);
            b[0][2 * q][0] = r0; b[0][2 * q + 1][0] = r1;
            b[0][2 * q][1] = r2; b[0][2 * q + 1][1] = r3;
        }
    }

    int g = 0;   // global step counter, continuous across tiles
    #pragma unroll 1
    for (int tj = 0; tj < ntiles; tj++) {
        int tile = bid + tj * grid;
        int rt = tile & 127, ct = tile >> 7;

        const char* gA = (const char*)g_A + (size_t)rt * K_TILES * TILE_BYTES;
        const char* gB = (const char*)g_B + (size_t)ct * K_TILES * TILE_BYTES;
        // next tile's bases (for the producer at kt==15)
        int tilen = tile + grid;
        const char* gAn = (const char*)g_A + (size_t)((tilen & 127) * K_TILES) * TILE_BYTES;
        const char* gBn = (const char*)g_B + (size_t)((tilen >> 7) * K_TILES) * TILE_BYTES;

        uint32_t acc[4][8][2] = {};   // f16x2 accumulators

        #pragma unroll 1
        for (int kt = 0; kt < K_TILES; kt++, g++) {
            int s = g & 1;

            // producer (rotating warp g&3, lane 0): issue TMA for step g+1
            if (wid == (g & 3) && lane == 0 && g + 1 < total_steps) {
                int gp = g + 1;
                int sn = gp & 1;
                MBAR_WAIT(empty0 + sn * 8, ((gp >> 1) & 1) ^ 1);
                const char* pA = (kt < K_TILES - 1) ? gA + (kt + 1) * TILE_BYTES : gAn;
                const char* pB = (kt < K_TILES - 1) ? gB + (kt + 1) * TILE_BYTES : gBn;
                uint32_t st = sdata + sn * STAGE_BYTES;
                MBAR_EXPECT_TX(full0 + sn * 8, STAGE_BYTES);
                bulk_g2s(st,              pA, TILE_BYTES, full0 + sn * 8);
                bulk_g2s(st + TILE_BYTES, pB, TILE_BYTES, full0 + sn * 8);
            }

            uint32_t abase = sdata + (uint32_t)s * STAGE_BYTES + arow0;
            uint32_t bbase = sdata + (uint32_t)s * STAGE_BYTES + TILE_BYTES + brow0;

            #pragma unroll
            for (int ks = 0; ks < 4; ks++) {
                int cur = ks & 1;
                int nxt = cur ^ 1;
                if (ks < 3) {
                    // prefetch ks+1 fragments from the current stage
                    uint32_t col = ((uint32_t)((ks + 1) * 32) + lh) ^ rxor;
                    #pragma unroll
                    for (int i = 0; i < 4; i++)
                        ldsm4(a[nxt][i][0], a[nxt][i][1], a[nxt][i][2], a[nxt][i][3],
                              abase + (uint32_t)(i * 16 * 128) + col);
                    #pragma unroll
                    for (int q = 0; q < 4; q++) {
                        uint32_t r0, r1, r2, r3;
                        ldsm4(r0, r1, r2, r3, bbase + (uint32_t)(q * 16 * 128) + col);
                        b[nxt][2 * q][0] = r0; b[nxt][2 * q + 1][0] = r1;
                        b[nxt][2 * q][1] = r2; b[nxt][2 * q + 1][1] = r3;
                    }
                    // last read of stage s: release it early for more TMA lead
                    if (ks == 2 && lane == 0) MBAR_ARRIVE(empty0 + s * 8);
                } else if (g + 1 < total_steps) {
                    // cross-step: wait for step g+1's stage (TMA issued a full step
                    // ago) and prime its ks=0 fragments under this step's mma drain.
                    int sn = s ^ 1;
                    MBAR_WAIT(full0 + sn * 8, ((g + 1) >> 1) & 1);
                    uint32_t abn = sdata + (uint32_t)sn * STAGE_BYTES + arow0;
                    uint32_t bbn = sdata + (uint32_t)sn * STAGE_BYTES + TILE_BYTES + brow0;
                    uint32_t col = lh ^ rxor;
                    #pragma unroll
                    for (int i = 0; i < 4; i++)
                        ldsm4(a[nxt][i][0], a[nxt][i][1], a[nxt][i][2], a[nxt][i][3],
                              abn + (uint32_t)(i * 16 * 128) + col);
                    #pragma unroll
                    for (int q = 0; q < 4; q++) {
                        uint32_t r0, r1, r2, r3;
                        ldsm4(r0, r1, r2, r3, bbn + (uint32_t)(q * 16 * 128) + col);
                        b[nxt][2 * q][0] = r0; b[nxt][2 * q + 1][0] = r1;
                        b[nxt][2 * q][1] = r2; b[nxt][2 * q + 1][1] = r3;
                    }
                }
                #pragma unroll
                for (int i = 0; i < 4; i++)
                    #pragma unroll
                    for (int j = 0; j < 8; j++)
                        mma_f16acc(acc[i][j], a[cur][i], b[cur][j]);
            }
        }

        // ---------------- epilogue for this tile: out = xsq + wsq - 2*acc ----------------
        // Next tile's ks=0 fragments are already in registers; TMAs keep flowing.
        int m0 = rt * BM + wm * 64;
        int n0 = ct * BN + wn * 64;
        int r = lane >> 2;
        int c2 = (lane & 3) * 2;

        #pragma unroll
        for (int i = 0; i < 4; i++) {
            int mA = m0 + i * 16 + r;
            float xs0 = __ldg(&g_xsq[mA]);
            float xs1 = __ldg(&g_xsq[mA + 8]);
            float* row0 = out + (size_t)mA * UDIM + n0;
            float* row1 = row0 + (size_t)8 * UDIM;
            #pragma unroll
            for (int j = 0; j < 8; j++) {
                float w0 = __ldg(&g_wsq[n0 + j * 8 + c2]);
                float w1 = __ldg(&g_wsq[n0 + j * 8 + c2 + 1]);
                float2 p0 = __half22float2(*reinterpret_cast<__half2*>(&acc[i][j][0]));
                float2 p1 = __half22float2(*reinterpret_cast<__half2*>(&acc[i][j][1]));
                float2 v0, v1;
                v0.x = xs0 + w0 - 2.0f * p0.x;
                v0.y = xs0 + w1 - 2.0f * p0.y;
                v1.x = xs1 + w0 - 2.0f * p1.x;
                v1.y = xs1 + w1 - 2.0f * p1.y;
                *reinterpret_cast<float2*>(row0 + j * 8 + c2) = v0;
                *reinterpret_cast<float2*>(row1 + j * 8 + c2) = v1;
            }
        }
    }
}

// ------------------- launch -------------------
extern "C" void kernel_launch(void* const* d_in, const int* in_sizes, int n_in,
                              void* d_out, int out_size) {
    (void)in_sizes; (void)n_in; (void)out_size;
    const float* x = (const float*)d_in[0];   // [16384, 1024]
    const float* w = (const float*)d_in[1];   // [4096, 1024]
    float* out = (float*)d_out;               // [16384, 4096]

    cudaFuncSetAttribute(gemm_kernel, cudaFuncAttributeMaxDynamicSharedMemorySize, SMEM_TOTAL);

    int sms = 152;
    cudaDeviceGetAttribute(&sms, cudaDevAttrMultiProcessorCount, 0);
    int grid = 3 * sms;
    if (grid > TOTAL_TILES) grid = TOTAL_TILES;

    convert_kernel<<<(NROWS + UDIM) / 8, 256>>>(x, w);
    gemm_kernel<<<grid, 128, SMEM_TOTAL>>>(out);
}